// round 1
// baseline (speedup 1.0000x reference)
#include <cuda_runtime.h>
#include <math.h>

// Problem constants
// B=256, TH=32, TF=16, S=512, A=128, R=1, F=1024, L=2, T=2*TH+1=65
#define NB   256
#define NTH  32
#define NTF  16
#define NS   512
#define NA   128
#define NF   1024
#define NG   3072   // 3*F
#define NT   65

// ---------------- scratch (device globals; no allocations allowed) -------------
__device__ float g_xs[NT * NB * NF];      // layer-1 input sequence [t][b][f]
__device__ float g_seq1[NT * NB * NF];    // layer-1 output sequence
__device__ float g_gi[NT * NB * NG];      // precomputed input gates for a layer
__device__ float g_sbuf[NB * NTH * NF];   // state embeddings (b,t major)
__device__ float g_abuf[NB * NTH * NF];   // action embeddings
__device__ float g_H[2 * NB * NF];        // hidden states, layer 0 / layer 1
__device__ float g_gh[NB * NG];           // per-step hidden-gate GEMM out
__device__ float g_gis[NB * NG];          // per-step input-gate GEMM out (future loop)
__device__ float g_x[NB * NF];            // per-step embedded input (future loop)

// ---------------- GEMM: C[M,N] = act(A[M,K] * W[N,K]^T + bias) -----------------
// Both A and W are K-contiguous (row-major), which matches every x @ W.T in the
// model. Two instantiations: 128x128x8 (8x8 micro) for big parallel GEMMs,
// 64x64x16 (4x4 micro) for the M=256 recurrent steps (192 blocks -> fills SMs).
// All M,N,K used are exact multiples of the tile dims (checked host-side).
template<int BM, int BN, int BK, int TM, int TN, int ACT>
__global__ __launch_bounds__(256)
void gemm_tn(const float* __restrict__ A, int lda,
             const float* __restrict__ W, int ldw,
             const float* __restrict__ bias,
             float* __restrict__ C, int ldc,
             int K)
{
    __shared__ __align__(16) float As[BK][BM];
    __shared__ __align__(16) float Bs[BK][BN];

    const int tid = threadIdx.x;
    const int bm = blockIdx.y * BM;
    const int bn = blockIdx.x * BN;

    // loaders: BM*BK == BN*BK == 1024 floats == 256 threads * 1 float4
    constexpr int K4 = BK / 4;
    const int lr = tid / K4;          // row within tile (BM==BN for both configs)
    const int lc = (tid % K4) * 4;    // k offset within tile

    const int tx = tid % (BN / TN);
    const int ty = tid / (BN / TN);

    float acc[TM][TN];
#pragma unroll
    for (int i = 0; i < TM; i++)
#pragma unroll
        for (int j = 0; j < TN; j++) acc[i][j] = 0.f;

    const float* Aptr = A + (size_t)(bm + lr) * lda + lc;
    const float* Wptr = W + (size_t)(bn + lr) * ldw + lc;

    for (int k0 = 0; k0 < K; k0 += BK) {
        float4 av = *reinterpret_cast<const float4*>(Aptr + k0);
        float4 wv = *reinterpret_cast<const float4*>(Wptr + k0);
        As[lc + 0][lr] = av.x; As[lc + 1][lr] = av.y;
        As[lc + 2][lr] = av.z; As[lc + 3][lr] = av.w;
        Bs[lc + 0][lr] = wv.x; Bs[lc + 1][lr] = wv.y;
        Bs[lc + 2][lr] = wv.z; Bs[lc + 3][lr] = wv.w;
        __syncthreads();

#pragma unroll
        for (int kk = 0; kk < BK; kk++) {
            float ar[TM], br[TN];
#pragma unroll
            for (int i = 0; i < TM; i += 4)
                *reinterpret_cast<float4*>(&ar[i]) =
                    *reinterpret_cast<const float4*>(&As[kk][ty * TM + i]);
#pragma unroll
            for (int j = 0; j < TN; j += 4)
                *reinterpret_cast<float4*>(&br[j]) =
                    *reinterpret_cast<const float4*>(&Bs[kk][tx * TN + j]);
#pragma unroll
            for (int i = 0; i < TM; i++)
#pragma unroll
                for (int j = 0; j < TN; j++)
                    acc[i][j] = fmaf(ar[i], br[j], acc[i][j]);
        }
        __syncthreads();
    }

#pragma unroll
    for (int i = 0; i < TM; i++) {
        float* Crow = C + (size_t)(bm + ty * TM + i) * ldc + bn + tx * TN;
#pragma unroll
        for (int j = 0; j < TN; j++) {
            float v = acc[i][j];
            if (bias) v += bias[bn + tx * TN + j];
            if (ACT == 1) v = tanhf(v);
            Crow[j] = v;
        }
    }
}

// ---------------- fused GRU gates: h' = (1-z)*n + z*h --------------------------
// gi/gh are WITHOUT bias; bih/bhh added here. In-place h update is safe
// (elementwise in h). Optionally also writes h' into a sequence buffer.
__global__ void gru_fuse(const float* __restrict__ gi, const float* __restrict__ gh,
                         const float* __restrict__ bih, const float* __restrict__ bhh,
                         float* __restrict__ h, float* __restrict__ seq_out)
{
    int idx = blockIdx.x * blockDim.x + threadIdx.x;   // < NB*NF
    int b = idx >> 10;
    int j = idx & (NF - 1);
    const float* gib = gi + (size_t)b * NG;
    const float* ghb = gh + (size_t)b * NG;

    float ir = gib[j]            + bih[j];
    float iz = gib[NF + j]       + bih[NF + j];
    float in_ = gib[2 * NF + j]  + bih[2 * NF + j];
    float hr = ghb[j]            + bhh[j];
    float hz = ghb[NF + j]       + bhh[NF + j];
    float hn = ghb[2 * NF + j]   + bhh[2 * NF + j];

    float r = 1.f / (1.f + expf(-(ir + hr)));
    float z = 1.f / (1.f + expf(-(iz + hz)));
    float n = tanhf(in_ + r * hn);
    float hv = h[idx];
    float out = (1.f - z) * n + z * hv;
    h[idx] = out;
    if (seq_out) seq_out[idx] = out;
}

// ---------------- interleave prefix: xs[2t]=s_emb_t, xs[2t+1]=a_emb_t ----------
__global__ void interleave_k(const float* __restrict__ sbuf,
                             const float* __restrict__ abuf,
                             float* __restrict__ xs)
{
    int idx = blockIdx.x * blockDim.x + threadIdx.x;   // < 64*NB*NF
    int t = idx >> 18;                 // /(NB*NF)
    int rem = idx & (NB * NF - 1);
    int b = rem >> 10;
    int f = rem & (NF - 1);
    int u = t >> 1;
    const float* src = (t & 1) ? abuf : sbuf;
    xs[idx] = src[(size_t)(b * NTH + u) * NF + f];
}

// ---------------- reward projection: out[b,step] = sigmoid(h . Wr + br) --------
__global__ void rproj_k(const float* __restrict__ H1, const float* __restrict__ Wr,
                        const float* __restrict__ br, float* __restrict__ out_r,
                        int step)
{
    __shared__ float red[256];
    int b = blockIdx.x;
    float p = 0.f;
    for (int k = threadIdx.x; k < NF; k += 256)
        p += H1[(size_t)b * NF + k] * Wr[k];
    red[threadIdx.x] = p;
    __syncthreads();
    for (int s = 128; s > 0; s >>= 1) {
        if (threadIdx.x < s) red[threadIdx.x] += red[threadIdx.x + s];
        __syncthreads();
    }
    if (threadIdx.x == 0)
        out_r[b * NTF + step] = 1.f / (1.f + expf(-(red[0] + br[0])));
}

__global__ void zero_k(float* p, int n)
{
    int i = blockIdx.x * blockDim.x + threadIdx.x;
    if (i < n) p[i] = 0.f;
}

// ---------------- host-side GEMM dispatcher ------------------------------------
static inline void gemm(const float* A, int lda, const float* W, int ldw,
                        const float* bias, float* C, int ldc,
                        int M, int N, int K, int act)
{
    if ((M % 128 == 0) && (N % 128 == 0) && M >= 1024) {
        dim3 grid(N / 128, M / 128);
        if (act)
            gemm_tn<128, 128, 8, 8, 8, 1><<<grid, 256>>>(A, lda, W, ldw, bias, C, ldc, K);
        else
            gemm_tn<128, 128, 8, 8, 8, 0><<<grid, 256>>>(A, lda, W, ldw, bias, C, ldc, K);
    } else {
        dim3 grid(N / 64, M / 64);
        if (act)
            gemm_tn<64, 64, 16, 4, 4, 1><<<grid, 256>>>(A, lda, W, ldw, bias, C, ldc, K);
        else
            gemm_tn<64, 64, 16, 4, 4, 0><<<grid, 256>>>(A, lda, W, ldw, bias, C, ldc, K);
    }
}

extern "C" void kernel_launch(void* const* d_in, const int* in_sizes, int n_in,
                              void* d_out, int out_size)
{
    (void)in_sizes; (void)n_in; (void)out_size;
    const float* history_s = (const float*)d_in[0];   // [B,TH,S]
    const float* history_a = (const float*)d_in[1];   // [B,TH,A]
    const float* present_s = (const float*)d_in[2];   // [B,S]
    const float* future_a  = (const float*)d_in[3];   // [B,TF,A]
    const float* Ws  = (const float*)d_in[4];         // [F,S]
    const float* bs  = (const float*)d_in[5];         // [F]
    const float* Wa  = (const float*)d_in[6];         // [F,A]
    const float* ba  = (const float*)d_in[7];         // [F]
    const float* Wih = (const float*)d_in[8];         // [L,3F,F]
    const float* Whh = (const float*)d_in[9];         // [L,3F,F]
    const float* bih = (const float*)d_in[10];        // [L,3F]
    const float* bhh = (const float*)d_in[11];        // [L,3F]
    const float* Wr  = (const float*)d_in[12];        // [1,F]
    const float* br  = (const float*)d_in[13];        // [1]
    const float* Ws2 = (const float*)d_in[14];        // [S,F]
    const float* bs2 = (const float*)d_in[15];        // [S]

    float* out_r = (float*)d_out;                     // [B,TF,1]
    float* out_s = (float*)d_out + NB * NTF;          // [B,TF,S]

    float *xs, *seq1, *gi, *sbuf, *abuf, *H, *gh, *gis, *xbuf;
    cudaGetSymbolAddress((void**)&xs,   g_xs);
    cudaGetSymbolAddress((void**)&seq1, g_seq1);
    cudaGetSymbolAddress((void**)&gi,   g_gi);
    cudaGetSymbolAddress((void**)&sbuf, g_sbuf);
    cudaGetSymbolAddress((void**)&abuf, g_abuf);
    cudaGetSymbolAddress((void**)&H,    g_H);
    cudaGetSymbolAddress((void**)&gh,   g_gh);
    cudaGetSymbolAddress((void**)&gis,  g_gis);
    cudaGetSymbolAddress((void**)&xbuf, g_x);

    // 0) zero hidden states
    zero_k<<<(2 * NB * NF + 255) / 256, 256>>>(H, 2 * NB * NF);

    // 1) embeddings
    gemm(history_s, NS, Ws, NS, bs, sbuf, NF, NB * NTH, NF, NS, 1);        // tanh(s@Ws^T+bs)
    gemm(history_a, NA, Wa, NA, ba, abuf, NF, NB * NTH, NF, NA, 1);        // tanh(a@Wa^T+ba)
    gemm(present_s, NS, Ws, NS, bs, xs + (size_t)64 * NB * NF, NF,
         NB, NF, NS, 1);                                                   // present -> xs[64]
    interleave_k<<<(64 * NB * NF) / 256, 256>>>(sbuf, abuf, xs);

    const float* Wih0 = Wih;            const float* Wih1 = Wih + (size_t)NG * NF;
    const float* Whh0 = Whh;            const float* Whh1 = Whh + (size_t)NG * NF;
    const float* bih0 = bih;            const float* bih1 = bih + NG;
    const float* bhh0 = bhh;            const float* bhh1 = bhh + NG;
    float* H0 = H;
    float* H1 = H + NB * NF;

    // 2) layer 1 over the prefix: hoisted input-gate GEMM + sequential h-gates
    gemm(xs, NF, Wih0, NF, nullptr, gi, NG, NT * NB, NG, NF, 0);
    for (int t = 0; t < NT; t++) {
        gemm(H0, NF, Whh0, NF, nullptr, gh, NG, NB, NG, NF, 0);
        gru_fuse<<<(NB * NF) / 256, 256>>>(gi + (size_t)t * NB * NG, gh,
                                           bih0, bhh0, H0,
                                           seq1 + (size_t)t * NB * NF);
    }

    // 3) layer 2 over the prefix (only final hidden needed)
    gemm(seq1, NF, Wih1, NF, nullptr, gi, NG, NT * NB, NG, NF, 0);
    for (int t = 0; t < NT; t++) {
        gemm(H1, NF, Whh1, NF, nullptr, gh, NG, NB, NG, NF, 0);
        gru_fuse<<<(NB * NF) / 256, 256>>>(gi + (size_t)t * NB * NG, gh,
                                           bih1, bhh1, H1, nullptr);
    }

    // helper: one GRU cell for the future loop (x is [B,F] with lda=NF)
    auto cell = [&](const float* x, int layer) {
        const float* Wih_l = layer ? Wih1 : Wih0;
        const float* Whh_l = layer ? Whh1 : Whh0;
        const float* bih_l = layer ? bih1 : bih0;
        const float* bhh_l = layer ? bhh1 : bhh0;
        float* Hl = layer ? H1 : H0;
        gemm(x,  NF, Wih_l, NF, nullptr, gis, NG, NB, NG, NF, 0);
        gemm(Hl, NF, Whh_l, NF, nullptr, gh,  NG, NB, NG, NF, 0);
        gru_fuse<<<(NB * NF) / 256, 256>>>(gis, gh, bih_l, bhh_l, Hl, nullptr);
    };

    // 4) future rollout
    for (int i = 0; i < NTF; i++) {
        // x = tanh(future_a[:,i,:] @ Wa^T + ba)
        gemm(future_a + (size_t)i * NA, NTF * NA, Wa, NA, ba, xbuf, NF,
             NB, NF, NA, 1);
        cell(xbuf, 0);
        cell(H0, 1);

        // reward + predicted state
        rproj_k<<<NB, 256>>>(H1, Wr, br, out_r, i);
        gemm(H1, NF, Ws2, NF, bs2, out_s + (size_t)i * NS, NTF * NS,
             NB, NS, NF, 1);                           // tanh -> written to output

        // feed tanh(state embedding of predicted state)
        gemm(out_s + (size_t)i * NS, NTF * NS, Ws, NS, bs, xbuf, NF,
             NB, NF, NS, 1);
        cell(xbuf, 0);
        cell(H0, 1);
    }
}

// round 2
// speedup vs baseline: 1.0000x; 1.0000x over previous
#include <cuda_runtime.h>
#include <math.h>

// Problem constants
// B=256, TH=32, TF=16, S=512, A=128, R=1, F=1024, L=2, T=2*TH+1=65
#define NB   256
#define NTH  32
#define NTF  16
#define NS   512
#define NA   128
#define NF   1024
#define NG   3072   // 3*F
#define NT   65

// ---------------- scratch (device globals; no allocations allowed) -------------
__device__ float g_xs[NT * NB * NF];      // layer-1 input sequence [t][b][f]
__device__ float g_seq1[NT * NB * NF];    // layer-1 output sequence
__device__ float g_gi[NT * NB * NG];      // precomputed input gates for a layer
__device__ float g_sbuf[NB * NTH * NF];   // state embeddings (b,t major)
__device__ float g_abuf[NB * NTH * NF];   // action embeddings
__device__ float g_H[2 * NB * NF];        // hidden states, layer 0 / layer 1
__device__ float g_gh[NB * NG];           // per-step hidden-gate GEMM out
__device__ float g_gis[NB * NG];          // per-step input-gate GEMM out (future loop)
__device__ float g_x[NB * NF];            // per-step embedded input (future loop)

// ---------------- GEMM: C[M,N] = act(A[M,K] * W[N,K]^T + bias) -----------------
// Both A and W are K-contiguous (row-major), which matches every x @ W.T in the
// model. Two instantiations: 128x128x8 (8x8 micro) for big parallel GEMMs,
// 64x64x16 (4x4 micro) for the M=256 recurrent steps (192 blocks -> fills SMs).
// All M,N,K used are exact multiples of the tile dims (checked host-side).
template<int BM, int BN, int BK, int TM, int TN, int ACT>
__global__ __launch_bounds__(256)
void gemm_tn(const float* __restrict__ A, int lda,
             const float* __restrict__ W, int ldw,
             const float* __restrict__ bias,
             float* __restrict__ C, int ldc,
             int K)
{
    __shared__ __align__(16) float As[BK][BM];
    __shared__ __align__(16) float Bs[BK][BN];

    const int tid = threadIdx.x;
    const int bm = blockIdx.y * BM;
    const int bn = blockIdx.x * BN;

    // loaders: BM*BK == BN*BK == 1024 floats == 256 threads * 1 float4
    constexpr int K4 = BK / 4;
    const int lr = tid / K4;          // row within tile (BM==BN for both configs)
    const int lc = (tid % K4) * 4;    // k offset within tile

    const int tx = tid % (BN / TN);
    const int ty = tid / (BN / TN);

    float acc[TM][TN];
#pragma unroll
    for (int i = 0; i < TM; i++)
#pragma unroll
        for (int j = 0; j < TN; j++) acc[i][j] = 0.f;

    const float* Aptr = A + (size_t)(bm + lr) * lda + lc;
    const float* Wptr = W + (size_t)(bn + lr) * ldw + lc;

    for (int k0 = 0; k0 < K; k0 += BK) {
        float4 av = *reinterpret_cast<const float4*>(Aptr + k0);
        float4 wv = *reinterpret_cast<const float4*>(Wptr + k0);
        As[lc + 0][lr] = av.x; As[lc + 1][lr] = av.y;
        As[lc + 2][lr] = av.z; As[lc + 3][lr] = av.w;
        Bs[lc + 0][lr] = wv.x; Bs[lc + 1][lr] = wv.y;
        Bs[lc + 2][lr] = wv.z; Bs[lc + 3][lr] = wv.w;
        __syncthreads();

#pragma unroll
        for (int kk = 0; kk < BK; kk++) {
            float ar[TM], br[TN];
#pragma unroll
            for (int i = 0; i < TM; i += 4)
                *reinterpret_cast<float4*>(&ar[i]) =
                    *reinterpret_cast<const float4*>(&As[kk][ty * TM + i]);
#pragma unroll
            for (int j = 0; j < TN; j += 4)
                *reinterpret_cast<float4*>(&br[j]) =
                    *reinterpret_cast<const float4*>(&Bs[kk][tx * TN + j]);
#pragma unroll
            for (int i = 0; i < TM; i++)
#pragma unroll
                for (int j = 0; j < TN; j++)
                    acc[i][j] = fmaf(ar[i], br[j], acc[i][j]);
        }
        __syncthreads();
    }

#pragma unroll
    for (int i = 0; i < TM; i++) {
        float* Crow = C + (size_t)(bm + ty * TM + i) * ldc + bn + tx * TN;
#pragma unroll
        for (int j = 0; j < TN; j++) {
            float v = acc[i][j];
            if (bias) v += bias[bn + tx * TN + j];
            if (ACT == 1) v = tanhf(v);
            Crow[j] = v;
        }
    }
}

// ---------------- fused GRU gates: h' = (1-z)*n + z*h --------------------------
// gi/gh are WITHOUT bias; bih/bhh added here. In-place h update is safe
// (elementwise in h). Optionally also writes h' into a sequence buffer.
__global__ void gru_fuse(const float* __restrict__ gi, const float* __restrict__ gh,
                         const float* __restrict__ bih, const float* __restrict__ bhh,
                         float* __restrict__ h, float* __restrict__ seq_out)
{
    int idx = blockIdx.x * blockDim.x + threadIdx.x;   // < NB*NF
    int b = idx >> 10;
    int j = idx & (NF - 1);
    const float* gib = gi + (size_t)b * NG;
    const float* ghb = gh + (size_t)b * NG;

    float ir = gib[j]            + bih[j];
    float iz = gib[NF + j]       + bih[NF + j];
    float in_ = gib[2 * NF + j]  + bih[2 * NF + j];
    float hr = ghb[j]            + bhh[j];
    float hz = ghb[NF + j]       + bhh[NF + j];
    float hn = ghb[2 * NF + j]   + bhh[2 * NF + j];

    float r = 1.f / (1.f + expf(-(ir + hr)));
    float z = 1.f / (1.f + expf(-(iz + hz)));
    float n = tanhf(in_ + r * hn);
    float hv = h[idx];
    float out = (1.f - z) * n + z * hv;
    h[idx] = out;
    if (seq_out) seq_out[idx] = out;
}

// ---------------- interleave prefix: xs[2t]=s_emb_t, xs[2t+1]=a_emb_t ----------
__global__ void interleave_k(const float* __restrict__ sbuf,
                             const float* __restrict__ abuf,
                             float* __restrict__ xs)
{
    int idx = blockIdx.x * blockDim.x + threadIdx.x;   // < 64*NB*NF
    int t = idx >> 18;                 // /(NB*NF)
    int rem = idx & (NB * NF - 1);
    int b = rem >> 10;
    int f = rem & (NF - 1);
    int u = t >> 1;
    const float* src = (t & 1) ? abuf : sbuf;
    xs[idx] = src[(size_t)(b * NTH + u) * NF + f];
}

// ---------------- reward projection: out[b,step] = sigmoid(h . Wr + br) --------
__global__ void rproj_k(const float* __restrict__ H1, const float* __restrict__ Wr,
                        const float* __restrict__ br, float* __restrict__ out_r,
                        int step)
{
    __shared__ float red[256];
    int b = blockIdx.x;
    float p = 0.f;
    for (int k = threadIdx.x; k < NF; k += 256)
        p += H1[(size_t)b * NF + k] * Wr[k];
    red[threadIdx.x] = p;
    __syncthreads();
    for (int s = 128; s > 0; s >>= 1) {
        if (threadIdx.x < s) red[threadIdx.x] += red[threadIdx.x + s];
        __syncthreads();
    }
    if (threadIdx.x == 0)
        out_r[b * NTF + step] = 1.f / (1.f + expf(-(red[0] + br[0])));
}

__global__ void zero_k(float* p, int n)
{
    int i = blockIdx.x * blockDim.x + threadIdx.x;
    if (i < n) p[i] = 0.f;
}

// ---------------- host-side GEMM dispatcher ------------------------------------
static inline void gemm(const float* A, int lda, const float* W, int ldw,
                        const float* bias, float* C, int ldc,
                        int M, int N, int K, int act)
{
    if ((M % 128 == 0) && (N % 128 == 0) && M >= 1024) {
        dim3 grid(N / 128, M / 128);
        if (act)
            gemm_tn<128, 128, 8, 8, 8, 1><<<grid, 256>>>(A, lda, W, ldw, bias, C, ldc, K);
        else
            gemm_tn<128, 128, 8, 8, 8, 0><<<grid, 256>>>(A, lda, W, ldw, bias, C, ldc, K);
    } else {
        dim3 grid(N / 64, M / 64);
        if (act)
            gemm_tn<64, 64, 16, 4, 4, 1><<<grid, 256>>>(A, lda, W, ldw, bias, C, ldc, K);
        else
            gemm_tn<64, 64, 16, 4, 4, 0><<<grid, 256>>>(A, lda, W, ldw, bias, C, ldc, K);
    }
}

extern "C" void kernel_launch(void* const* d_in, const int* in_sizes, int n_in,
                              void* d_out, int out_size)
{
    (void)in_sizes; (void)n_in; (void)out_size;
    const float* history_s = (const float*)d_in[0];   // [B,TH,S]
    const float* history_a = (const float*)d_in[1];   // [B,TH,A]
    const float* present_s = (const float*)d_in[2];   // [B,S]
    const float* future_a  = (const float*)d_in[3];   // [B,TF,A]
    const float* Ws  = (const float*)d_in[4];         // [F,S]
    const float* bs  = (const float*)d_in[5];         // [F]
    const float* Wa  = (const float*)d_in[6];         // [F,A]
    const float* ba  = (const float*)d_in[7];         // [F]
    const float* Wih = (const float*)d_in[8];         // [L,3F,F]
    const float* Whh = (const float*)d_in[9];         // [L,3F,F]
    const float* bih = (const float*)d_in[10];        // [L,3F]
    const float* bhh = (const float*)d_in[11];        // [L,3F]
    const float* Wr  = (const float*)d_in[12];        // [1,F]
    const float* br  = (const float*)d_in[13];        // [1]
    const float* Ws2 = (const float*)d_in[14];        // [S,F]
    const float* bs2 = (const float*)d_in[15];        // [S]

    float* out_r = (float*)d_out;                     // [B,TF,1]
    float* out_s = (float*)d_out + NB * NTF;          // [B,TF,S]

    float *xs, *seq1, *gi, *sbuf, *abuf, *H, *gh, *gis, *xbuf;
    cudaGetSymbolAddress((void**)&xs,   g_xs);
    cudaGetSymbolAddress((void**)&seq1, g_seq1);
    cudaGetSymbolAddress((void**)&gi,   g_gi);
    cudaGetSymbolAddress((void**)&sbuf, g_sbuf);
    cudaGetSymbolAddress((void**)&abuf, g_abuf);
    cudaGetSymbolAddress((void**)&H,    g_H);
    cudaGetSymbolAddress((void**)&gh,   g_gh);
    cudaGetSymbolAddress((void**)&gis,  g_gis);
    cudaGetSymbolAddress((void**)&xbuf, g_x);

    // 0) zero hidden states
    zero_k<<<(2 * NB * NF + 255) / 256, 256>>>(H, 2 * NB * NF);

    // 1) embeddings
    gemm(history_s, NS, Ws, NS, bs, sbuf, NF, NB * NTH, NF, NS, 1);        // tanh(s@Ws^T+bs)
    gemm(history_a, NA, Wa, NA, ba, abuf, NF, NB * NTH, NF, NA, 1);        // tanh(a@Wa^T+ba)
    gemm(present_s, NS, Ws, NS, bs, xs + (size_t)64 * NB * NF, NF,
         NB, NF, NS, 1);                                                   // present -> xs[64]
    interleave_k<<<(64 * NB * NF) / 256, 256>>>(sbuf, abuf, xs);

    const float* Wih0 = Wih;            const float* Wih1 = Wih + (size_t)NG * NF;
    const float* Whh0 = Whh;            const float* Whh1 = Whh + (size_t)NG * NF;
    const float* bih0 = bih;            const float* bih1 = bih + NG;
    const float* bhh0 = bhh;            const float* bhh1 = bhh + NG;
    float* H0 = H;
    float* H1 = H + NB * NF;

    // 2) layer 1 over the prefix: hoisted input-gate GEMM + sequential h-gates
    gemm(xs, NF, Wih0, NF, nullptr, gi, NG, NT * NB, NG, NF, 0);
    for (int t = 0; t < NT; t++) {
        gemm(H0, NF, Whh0, NF, nullptr, gh, NG, NB, NG, NF, 0);
        gru_fuse<<<(NB * NF) / 256, 256>>>(gi + (size_t)t * NB * NG, gh,
                                           bih0, bhh0, H0,
                                           seq1 + (size_t)t * NB * NF);
    }

    // 3) layer 2 over the prefix (only final hidden needed)
    gemm(seq1, NF, Wih1, NF, nullptr, gi, NG, NT * NB, NG, NF, 0);
    for (int t = 0; t < NT; t++) {
        gemm(H1, NF, Whh1, NF, nullptr, gh, NG, NB, NG, NF, 0);
        gru_fuse<<<(NB * NF) / 256, 256>>>(gi + (size_t)t * NB * NG, gh,
                                           bih1, bhh1, H1, nullptr);
    }

    // helper: one GRU cell for the future loop (x is [B,F] with lda=NF)
    auto cell = [&](const float* x, int layer) {
        const float* Wih_l = layer ? Wih1 : Wih0;
        const float* Whh_l = layer ? Whh1 : Whh0;
        const float* bih_l = layer ? bih1 : bih0;
        const float* bhh_l = layer ? bhh1 : bhh0;
        float* Hl = layer ? H1 : H0;
        gemm(x,  NF, Wih_l, NF, nullptr, gis, NG, NB, NG, NF, 0);
        gemm(Hl, NF, Whh_l, NF, nullptr, gh,  NG, NB, NG, NF, 0);
        gru_fuse<<<(NB * NF) / 256, 256>>>(gis, gh, bih_l, bhh_l, Hl, nullptr);
    };

    // 4) future rollout
    for (int i = 0; i < NTF; i++) {
        // x = tanh(future_a[:,i,:] @ Wa^T + ba)
        gemm(future_a + (size_t)i * NA, NTF * NA, Wa, NA, ba, xbuf, NF,
             NB, NF, NA, 1);
        cell(xbuf, 0);
        cell(H0, 1);

        // reward + predicted state
        rproj_k<<<NB, 256>>>(H1, Wr, br, out_r, i);
        gemm(H1, NF, Ws2, NF, bs2, out_s + (size_t)i * NS, NTF * NS,
             NB, NS, NF, 1);                           // tanh -> written to output

        // feed tanh(state embedding of predicted state)
        gemm(out_s + (size_t)i * NS, NTF * NS, Ws, NS, bs, xbuf, NF,
             NB, NF, NS, 1);
        cell(xbuf, 0);
        cell(H0, 1);
    }
}

// round 5
// speedup vs baseline: 3.1810x; 3.1809x over previous
#include <cuda_runtime.h>
#include <cuda_bf16.h>
#include <cstdint>
#include <math.h>

#define NB 256
#define NTH 32
#define NTF 16
#define NS 512
#define NA 128
#define NF 1024
#define NG 3072
#define NT 65

typedef __nv_bfloat16 bf16;

// ------------------------------ scratch globals -------------------------------
__device__ float g_gi [(size_t)NT * NB * NG];
__device__ float g_gh [NB * NG];
__device__ float g_gis[NB * NG];
__device__ float g_H  [2 * NB * NF];
__device__ bf16 g_H_hi[2 * NB * NF], g_H_lo[2 * NB * NF];
__device__ bf16 g_xs_hi [(size_t)NT * NB * NF], g_xs_lo [(size_t)NT * NB * NF];
__device__ bf16 g_seq_hi[(size_t)NT * NB * NF], g_seq_lo[(size_t)NT * NB * NF];
__device__ bf16 g_x_hi [NB * NF], g_x_lo [NB * NF];
__device__ bf16 g_fx_hi[NB * NTF * NF], g_fx_lo[NB * NTF * NF];
__device__ bf16 g_so_hi[NB * NS], g_so_lo[NB * NS];
__device__ bf16 g_sb_hi[NB * NTH * NF], g_sb_lo[NB * NTH * NF];
__device__ bf16 g_ab_hi[NB * NTH * NF], g_ab_lo[NB * NTH * NF];
__device__ bf16 g_hs_hi[NB * NTH * NS], g_hs_lo[NB * NTH * NS];
__device__ bf16 g_ha_hi[NB * NTH * NA], g_ha_lo[NB * NTH * NA];
__device__ bf16 g_ps_hi[NB * NS],       g_ps_lo[NB * NS];
__device__ bf16 g_fa_hi[NB * NTF * NA], g_fa_lo[NB * NTF * NA];
__device__ bf16 g_Ws_hi [NF * NS],     g_Ws_lo [NF * NS];
__device__ bf16 g_Wa_hi [NF * NA],     g_Wa_lo [NF * NA];
__device__ bf16 g_Wih_hi[2 * NG * NF], g_Wih_lo[2 * NG * NF];
__device__ bf16 g_Whh_hi[2 * NG * NF], g_Whh_lo[2 * NG * NF];
__device__ bf16 g_Ws2_hi[NS * NF],     g_Ws2_lo[NS * NF];

// ------------------------------- helpers --------------------------------------
__device__ __forceinline__ uint32_t smem_u32(const void* p) {
    uint32_t a;
    asm("{ .reg .u64 t; cvta.to.shared.u64 t, %1; cvt.u32.u64 %0, t; }" : "=r"(a) : "l"(p));
    return a;
}
__device__ __forceinline__ uint32_t lds32(uint32_t a) {
    uint32_t v;
    asm volatile("ld.shared.b32 %0, [%1];" : "=r"(v) : "r"(a));
    return v;
}
#define CPA(d, s) asm volatile("cp.async.cg.shared.global [%0], [%1], 16;" :: "r"(d), "l"(s))
#define CPA_COMMIT() asm volatile("cp.async.commit_group;" ::: "memory")
#define CPA_WAIT1() asm volatile("cp.async.wait_group 1;" ::: "memory")
#define CPA_WAIT0() asm volatile("cp.async.wait_group 0;" ::: "memory")

__device__ __forceinline__ void mma4(float* d, const uint32_t* a, uint32_t b0, uint32_t b1) {
    asm volatile(
        "mma.sync.aligned.m16n8k16.row.col.f32.bf16.bf16.f32 "
        "{%0,%1,%2,%3},{%4,%5,%6,%7},{%8,%9},{%0,%1,%2,%3};"
        : "+f"(d[0]), "+f"(d[1]), "+f"(d[2]), "+f"(d[3])
        : "r"(a[0]), "r"(a[1]), "r"(a[2]), "r"(a[3]), "r"(b0), "r"(b1));
}

struct GP {
    const bf16 *Ah, *Al, *Wh, *Wl;
    const float* bias;
    float* C;
    bf16 *Ohi, *Olo;
    long lda, ldc, ldo;
};

// C[M,N] = A[M,K] @ W[N,K]^T.  bf16 hi/lo 3-pass HMMA.  Block 128 x BN x 64,
// 4 warps, warp tile 64 x (BN/2).  MODE 0: fp32 C.  MODE 1: tanh(+bias) ->
// bf16 hi/lo.  MODE 3: MODE1 + fp32 C.  blockIdx.z picks p0/p1 (dual GEMM).
template<int BN, int MODE>
__global__ __launch_bounds__(128)
void mma_gemm(GP p0, GP p1, int K)
{
    const GP p = (blockIdx.z == 0) ? p0 : p1;
    extern __shared__ __align__(16) char sm[];
    constexpr int APL = 128 * 144;          // A plane bytes (row stride 144B)
    constexpr int BPL = BN * 144;
    constexpr int STAGE = 2 * APL + 2 * BPL;
    constexpr int WNT = BN / 16;            // n-tiles (8 cols) per warp

    const int tid = threadIdx.x, lane = tid & 31, warp = tid >> 5;
    const int wm = warp & 1, wn = warp >> 1;
    const int m0 = blockIdx.y * 128, n0 = blockIdx.x * BN;
    const uint32_t sb = smem_u32(sm);
    const int lq = lane >> 2;               // 0..7
    const int lr = (lane & 3);              // 0..3

    float acc[4][WNT][4];
    #pragma unroll
    for (int i = 0; i < 4; i++)
        #pragma unroll
        for (int j = 0; j < WNT; j++)
            #pragma unroll
            for (int q = 0; q < 4; q++) acc[i][j][q] = 0.f;

    auto load_stage = [&](int s, int k0) {
        uint32_t ab = sb + s * STAGE;
        #pragma unroll
        for (int v = tid; v < 1024; v += 128) {
            int row = v >> 3, q = v & 7;
            size_t g = (size_t)(m0 + row) * p.lda + k0 + q * 8;
            uint32_t d = ab + row * 144 + q * 16;
            CPA(d, p.Ah + g);
            CPA(d + APL, p.Al + g);
        }
        #pragma unroll
        for (int v = tid; v < BN * 8; v += 128) {
            int row = v >> 3, q = v & 7;
            size_t g = (size_t)(n0 + row) * K + k0 + q * 8;
            uint32_t d = ab + 2 * APL + row * 144 + q * 16;
            CPA(d, p.Wh + g);
            CPA(d + BPL, p.Wl + g);
        }
    };

    const int NC = K >> 6;
    load_stage(0, 0);
    CPA_COMMIT();

    for (int c = 0; c < NC; c++) {
        if (c + 1 < NC) { load_stage((c + 1) & 1, (c + 1) << 6); CPA_COMMIT(); CPA_WAIT1(); }
        else           { CPA_WAIT0(); }
        __syncthreads();

        const int s = c & 1;
        uint32_t aH = sb + s * STAGE, aL = aH + APL, bH = aL + APL, bL = bH + BPL;
        #pragma unroll
        for (int kk = 0; kk < 4; kk++) {
            const int kb = kk * 32 + lr * 4;     // byte offset in row
            uint32_t ah[4][4], al[4][4];
            #pragma unroll
            for (int mt = 0; mt < 4; mt++) {
                uint32_t r = (uint32_t)(wm * 64 + mt * 16 + lq) * 144 + kb;
                ah[mt][0] = lds32(aH + r);
                ah[mt][1] = lds32(aH + r + 8 * 144);
                ah[mt][2] = lds32(aH + r + 16);
                ah[mt][3] = lds32(aH + r + 8 * 144 + 16);
                al[mt][0] = lds32(aL + r);
                al[mt][1] = lds32(aL + r + 8 * 144);
                al[mt][2] = lds32(aL + r + 16);
                al[mt][3] = lds32(aL + r + 8 * 144 + 16);
            }
            #pragma unroll
            for (int nt = 0; nt < WNT; nt++) {
                uint32_t r = (uint32_t)(wn * (BN / 2) + nt * 8 + lq) * 144 + kb;
                uint32_t bh0 = lds32(bH + r), bh1 = lds32(bH + r + 16);
                uint32_t bl0 = lds32(bL + r), bl1 = lds32(bL + r + 16);
                #pragma unroll
                for (int mt = 0; mt < 4; mt++) {
                    mma4(acc[mt][nt], ah[mt], bh0, bh1);
                    mma4(acc[mt][nt], ah[mt], bl0, bl1);
                    mma4(acc[mt][nt], al[mt], bh0, bh1);
                }
            }
        }
        __syncthreads();
    }

    // epilogue
    #pragma unroll
    for (int mt = 0; mt < 4; mt++) {
        #pragma unroll
        for (int nt = 0; nt < WNT; nt++) {
            int gm = m0 + wm * 64 + mt * 16 + lq;
            int gn = n0 + wn * (BN / 2) + nt * 8 + lr * 2;
            float* a = acc[mt][nt];
            if (MODE == 0) {
                float2 v0; v0.x = a[0]; v0.y = a[1];
                float2 v1; v1.x = a[2]; v1.y = a[3];
                *reinterpret_cast<float2*>(p.C + (size_t)gm * p.ldc + gn) = v0;
                *reinterpret_cast<float2*>(p.C + (size_t)(gm + 8) * p.ldc + gn) = v1;
            } else {
                float b0 = p.bias[gn], b1 = p.bias[gn + 1];
                float v00 = tanhf(a[0] + b0), v01 = tanhf(a[1] + b1);
                float v10 = tanhf(a[2] + b0), v11 = tanhf(a[3] + b1);
                __nv_bfloat162 h0, l0, h1, l1;
                h0.x = __float2bfloat16(v00); h0.y = __float2bfloat16(v01);
                l0.x = __float2bfloat16(v00 - __bfloat162float(h0.x));
                l0.y = __float2bfloat16(v01 - __bfloat162float(h0.y));
                h1.x = __float2bfloat16(v10); h1.y = __float2bfloat16(v11);
                l1.x = __float2bfloat16(v10 - __bfloat162float(h1.x));
                l1.y = __float2bfloat16(v11 - __bfloat162float(h1.y));
                *reinterpret_cast<__nv_bfloat162*>(p.Ohi + (size_t)gm * p.ldo + gn) = h0;
                *reinterpret_cast<__nv_bfloat162*>(p.Olo + (size_t)gm * p.ldo + gn) = l0;
                *reinterpret_cast<__nv_bfloat162*>(p.Ohi + (size_t)(gm + 8) * p.ldo + gn) = h1;
                *reinterpret_cast<__nv_bfloat162*>(p.Olo + (size_t)(gm + 8) * p.ldo + gn) = l1;
                if (MODE == 3) {
                    float2 v0; v0.x = v00; v0.y = v01;
                    float2 v1; v1.x = v10; v1.y = v11;
                    *reinterpret_cast<float2*>(p.C + (size_t)gm * p.ldc + gn) = v0;
                    *reinterpret_cast<float2*>(p.C + (size_t)(gm + 8) * p.ldc + gn) = v1;
                }
            }
        }
    }
}

// ------------------------- fused GRU gates + hi/lo -----------------------------
__global__ void gru_fuse(const float* __restrict__ gi, const float* __restrict__ gh,
                         const float* __restrict__ bih, const float* __restrict__ bhh,
                         float* __restrict__ h, bf16* __restrict__ hhi, bf16* __restrict__ hlo,
                         bf16* __restrict__ shi, bf16* __restrict__ slo)
{
    int idx = blockIdx.x * blockDim.x + threadIdx.x;   // < NB*NF
    int b = idx >> 10, j = idx & (NF - 1);
    const float* gib = gi + (size_t)b * NG;
    const float* ghb = gh + (size_t)b * NG;
    float r = 1.f / (1.f + expf(-(gib[j] + bih[j] + ghb[j] + bhh[j])));
    float z = 1.f / (1.f + expf(-(gib[NF + j] + bih[NF + j] + ghb[NF + j] + bhh[NF + j])));
    float n = tanhf(gib[2 * NF + j] + bih[2 * NF + j] + r * (ghb[2 * NF + j] + bhh[2 * NF + j]));
    float out = (1.f - z) * n + z * h[idx];
    h[idx] = out;
    bf16 hi = __float2bfloat16(out);
    bf16 lo = __float2bfloat16(out - __bfloat162float(hi));
    hhi[idx] = hi; hlo[idx] = lo;
    if (shi) { shi[idx] = hi; slo[idx] = lo; }
}

__global__ void interleave_k(const bf16* __restrict__ sh, const bf16* __restrict__ sl,
                             const bf16* __restrict__ ah, const bf16* __restrict__ al,
                             bf16* __restrict__ xh, bf16* __restrict__ xl)
{
    int i = blockIdx.x * blockDim.x + threadIdx.x;  // bf162 units over 64*NB*NF/2
    int t = i / (NB * NF / 2);
    int rem = i % (NB * NF / 2);
    int b = rem / (NF / 2), f2 = rem % (NF / 2);
    int u = t >> 1;
    size_t src = (size_t)(b * NTH + u) * (NF / 2) + f2;
    const uint32_t* ph = reinterpret_cast<const uint32_t*>((t & 1) ? ah : sh);
    const uint32_t* pl = reinterpret_cast<const uint32_t*>((t & 1) ? al : sl);
    reinterpret_cast<uint32_t*>(xh)[i] = ph[src];
    reinterpret_cast<uint32_t*>(xl)[i] = pl[src];
}

__global__ void rproj_k(const float* __restrict__ H1, const float* __restrict__ Wr,
                        const float* __restrict__ br, float* __restrict__ out_r, int step)
{
    __shared__ float red[256];
    int b = blockIdx.x;
    float p = 0.f;
    for (int k = threadIdx.x; k < NF; k += 256) p += H1[(size_t)b * NF + k] * Wr[k];
    red[threadIdx.x] = p;
    __syncthreads();
    for (int s = 128; s > 0; s >>= 1) {
        if (threadIdx.x < s) red[threadIdx.x] += red[threadIdx.x + s];
        __syncthreads();
    }
    if (threadIdx.x == 0)
        out_r[b * NTF + step] = 1.f / (1.f + expf(-(red[0] + br[0])));
}

__global__ void split_k(const float* __restrict__ x, bf16* __restrict__ hi,
                        bf16* __restrict__ lo, int n)
{
    int i = blockIdx.x * blockDim.x + threadIdx.x;
    if (i < n) {
        float v = x[i];
        bf16 h = __float2bfloat16(v);
        hi[i] = h;
        lo[i] = __float2bfloat16(v - __bfloat162float(h));
    }
}

__global__ void zeroH_k(float* h, bf16* hi, bf16* lo, int n)
{
    int i = blockIdx.x * blockDim.x + threadIdx.x;
    if (i < n) { h[i] = 0.f; hi[i] = __float2bfloat16(0.f); lo[i] = __float2bfloat16(0.f); }
}

// ----------------------------------- host --------------------------------------
static const int SMEM128 = 2 * (2 * 128 * 144 + 2 * 128 * 144);   // 147456
static const int SMEM64  = 2 * (2 * 128 * 144 + 2 *  64 * 144);   // 110592

static inline GP mkGP(const bf16* Ah, const bf16* Al, long lda,
                      const bf16* Wh, const bf16* Wl,
                      const float* bias, float* C, long ldc,
                      bf16* Ohi, bf16* Olo, long ldo)
{
    GP p; p.Ah = Ah; p.Al = Al; p.Wh = Wh; p.Wl = Wl; p.bias = bias;
    p.C = C; p.Ohi = Ohi; p.Olo = Olo; p.lda = lda; p.ldc = ldc; p.ldo = ldo;
    return p;
}

extern "C" void kernel_launch(void* const* d_in, const int* in_sizes, int n_in,
                              void* d_out, int out_size)
{
    (void)in_sizes; (void)n_in; (void)out_size;
    const float* history_s = (const float*)d_in[0];
    const float* history_a = (const float*)d_in[1];
    const float* present_s = (const float*)d_in[2];
    const float* future_a  = (const float*)d_in[3];
    const float* Ws  = (const float*)d_in[4];
    const float* bs  = (const float*)d_in[5];
    const float* Wa  = (const float*)d_in[6];
    const float* ba  = (const float*)d_in[7];
    const float* Wih = (const float*)d_in[8];
    const float* Whh = (const float*)d_in[9];
    const float* bih = (const float*)d_in[10];
    const float* bhh = (const float*)d_in[11];
    const float* Wr  = (const float*)d_in[12];
    const float* br  = (const float*)d_in[13];
    const float* Ws2 = (const float*)d_in[14];
    const float* bs2 = (const float*)d_in[15];

    float* out_r = (float*)d_out;
    float* out_s = (float*)d_out + NB * NTF;

    float *gi, *gh, *gis, *H;
    bf16 *Hhi, *Hlo, *xshi, *xslo, *seqhi, *seqlo, *xhi, *xlo, *fxhi, *fxlo, *sohi, *solo;
    bf16 *sbhi, *sblo, *abhi, *ablo;
    bf16 *hshi, *hslo, *hahi, *halo, *pshi, *pslo, *fahi, *falo;
    bf16 *Wshi, *Wslo, *Wahi, *Walo, *Wihhi, *Wihlo, *Whhhi, *Whhlo, *Ws2hi, *Ws2lo;
    cudaGetSymbolAddress((void**)&gi, g_gi);     cudaGetSymbolAddress((void**)&gh, g_gh);
    cudaGetSymbolAddress((void**)&gis, g_gis);   cudaGetSymbolAddress((void**)&H, g_H);
    cudaGetSymbolAddress((void**)&Hhi, g_H_hi);  cudaGetSymbolAddress((void**)&Hlo, g_H_lo);
    cudaGetSymbolAddress((void**)&xshi, g_xs_hi); cudaGetSymbolAddress((void**)&xslo, g_xs_lo);
    cudaGetSymbolAddress((void**)&seqhi, g_seq_hi); cudaGetSymbolAddress((void**)&seqlo, g_seq_lo);
    cudaGetSymbolAddress((void**)&xhi, g_x_hi);  cudaGetSymbolAddress((void**)&xlo, g_x_lo);
    cudaGetSymbolAddress((void**)&fxhi, g_fx_hi); cudaGetSymbolAddress((void**)&fxlo, g_fx_lo);
    cudaGetSymbolAddress((void**)&sohi, g_so_hi); cudaGetSymbolAddress((void**)&solo, g_so_lo);
    cudaGetSymbolAddress((void**)&sbhi, g_sb_hi); cudaGetSymbolAddress((void**)&sblo, g_sb_lo);
    cudaGetSymbolAddress((void**)&abhi, g_ab_hi); cudaGetSymbolAddress((void**)&ablo, g_ab_lo);
    cudaGetSymbolAddress((void**)&hshi, g_hs_hi); cudaGetSymbolAddress((void**)&hslo, g_hs_lo);
    cudaGetSymbolAddress((void**)&hahi, g_ha_hi); cudaGetSymbolAddress((void**)&halo, g_ha_lo);
    cudaGetSymbolAddress((void**)&pshi, g_ps_hi); cudaGetSymbolAddress((void**)&pslo, g_ps_lo);
    cudaGetSymbolAddress((void**)&fahi, g_fa_hi); cudaGetSymbolAddress((void**)&falo, g_fa_lo);
    cudaGetSymbolAddress((void**)&Wshi, g_Ws_hi); cudaGetSymbolAddress((void**)&Wslo, g_Ws_lo);
    cudaGetSymbolAddress((void**)&Wahi, g_Wa_hi); cudaGetSymbolAddress((void**)&Walo, g_Wa_lo);
    cudaGetSymbolAddress((void**)&Wihhi, g_Wih_hi); cudaGetSymbolAddress((void**)&Wihlo, g_Wih_lo);
    cudaGetSymbolAddress((void**)&Whhhi, g_Whh_hi); cudaGetSymbolAddress((void**)&Whhlo, g_Whh_lo);
    cudaGetSymbolAddress((void**)&Ws2hi, g_Ws2_hi); cudaGetSymbolAddress((void**)&Ws2lo, g_Ws2_lo);

    cudaFuncSetAttribute(mma_gemm<128, 0>, cudaFuncAttributeMaxDynamicSharedMemorySize, SMEM128);
    cudaFuncSetAttribute(mma_gemm<128, 1>, cudaFuncAttributeMaxDynamicSharedMemorySize, SMEM128);
    cudaFuncSetAttribute(mma_gemm<64, 0>,  cudaFuncAttributeMaxDynamicSharedMemorySize, SMEM64);
    cudaFuncSetAttribute(mma_gemm<64, 1>,  cudaFuncAttributeMaxDynamicSharedMemorySize, SMEM64);
    cudaFuncSetAttribute(mma_gemm<64, 3>,  cudaFuncAttributeMaxDynamicSharedMemorySize, SMEM64);

    auto split = [&](const float* x, bf16* hi, bf16* lo, long n) {
        split_k<<<(int)((n + 255) / 256), 256>>>(x, hi, lo, (int)n);
    };
    split(history_s, hshi, hslo, (long)NB * NTH * NS);
    split(history_a, hahi, halo, (long)NB * NTH * NA);
    split(present_s, pshi, pslo, (long)NB * NS);
    split(future_a,  fahi, falo, (long)NB * NTF * NA);
    split(Ws,  Wshi,  Wslo,  (long)NF * NS);
    split(Wa,  Wahi,  Walo,  (long)NF * NA);
    split(Wih, Wihhi, Wihlo, (long)2 * NG * NF);
    split(Whh, Whhhi, Whhlo, (long)2 * NG * NF);
    split(Ws2, Ws2hi, Ws2lo, (long)NS * NF);
    zeroH_k<<<(2 * NB * NF + 255) / 256, 256>>>(H, Hhi, Hlo, 2 * NB * NF);

    const bf16 *Wih0h = Wihhi, *Wih0l = Wihlo;
    const bf16 *Wih1h = Wihhi + (size_t)NG * NF, *Wih1l = Wihlo + (size_t)NG * NF;
    const bf16 *Whh0h = Whhhi, *Whh0l = Whhlo;
    const bf16 *Whh1h = Whhhi + (size_t)NG * NF, *Whh1l = Whhlo + (size_t)NG * NF;
    const float *bih0 = bih, *bih1 = bih + NG, *bhh0 = bhh, *bhh1 = bhh + NG;
    float *H0 = H, *H1 = H + NB * NF;
    bf16 *H0hi = Hhi, *H0lo = Hlo, *H1hi = Hhi + NB * NF, *H1lo = Hlo + NB * NF;

    // embeddings (parallel)
    {   GP p = mkGP(hshi, hslo, NS, Wshi, Wslo, bs, nullptr, 0, sbhi, sblo, NF);
        mma_gemm<128, 1><<<dim3(NF / 128, (NB * NTH) / 128, 1), 128, SMEM128>>>(p, p, NS); }
    {   GP p = mkGP(hahi, halo, NA, Wahi, Walo, ba, nullptr, 0, abhi, ablo, NF);
        mma_gemm<128, 1><<<dim3(NF / 128, (NB * NTH) / 128, 1), 128, SMEM128>>>(p, p, NA); }
    {   GP p = mkGP(pshi, pslo, NS, Wshi, Wslo, bs, nullptr, 0,
                    xshi + (size_t)64 * NB * NF, xslo + (size_t)64 * NB * NF, NF);
        mma_gemm<64, 1><<<dim3(NF / 64, NB / 128, 1), 128, SMEM64>>>(p, p, NS); }
    {   // all 16 future action embeddings at once: [B*TF, A] -> [B*TF, F]
        GP p = mkGP(fahi, falo, NA, Wahi, Walo, ba, nullptr, 0, fxhi, fxlo, NF);
        mma_gemm<128, 1><<<dim3(NF / 128, (NB * NTF) / 128, 1), 128, SMEM128>>>(p, p, NA); }
    interleave_k<<<(64 * NB * NF / 2) / 256, 256>>>(sbhi, sblo, abhi, ablo, xshi, xslo);

    // layer 0 over prefix
    {   GP p = mkGP(xshi, xslo, NF, Wih0h, Wih0l, nullptr, gi, NG, nullptr, nullptr, 0);
        mma_gemm<128, 0><<<dim3(NG / 128, (NT * NB) / 128, 1), 128, SMEM128>>>(p, p, NF); }
    for (int t = 0; t < NT; t++) {
        GP p = mkGP(H0hi, H0lo, NF, Whh0h, Whh0l, nullptr, gh, NG, nullptr, nullptr, 0);
        mma_gemm<64, 0><<<dim3(NG / 64, NB / 128, 1), 128, SMEM64>>>(p, p, NF);
        gru_fuse<<<(NB * NF) / 256, 256>>>(gi + (size_t)t * NB * NG, gh, bih0, bhh0,
                                           H0, H0hi, H0lo,
                                           seqhi + (size_t)t * NB * NF,
                                           seqlo + (size_t)t * NB * NF);
    }
    // layer 1 over prefix
    {   GP p = mkGP(seqhi, seqlo, NF, Wih1h, Wih1l, nullptr, gi, NG, nullptr, nullptr, 0);
        mma_gemm<128, 0><<<dim3(NG / 128, (NT * NB) / 128, 1), 128, SMEM128>>>(p, p, NF); }
    for (int t = 0; t < NT; t++) {
        GP p = mkGP(H1hi, H1lo, NF, Whh1h, Whh1l, nullptr, gh, NG, nullptr, nullptr, 0);
        mma_gemm<64, 0><<<dim3(NG / 64, NB / 128, 1), 128, SMEM64>>>(p, p, NF);
        gru_fuse<<<(NB * NF) / 256, 256>>>(gi + (size_t)t * NB * NG, gh, bih1, bhh1,
                                           H1, H1hi, H1lo, nullptr, nullptr);
    }

    // one GRU cell: dual GEMM (gi from x, gh from h) + fuse
    auto cell = [&](const bf16* xh, const bf16* xl, long xlda, int layer) {
        GP pa = mkGP(xh, xl, xlda, layer ? Wih1h : Wih0h, layer ? Wih1l : Wih0l,
                     nullptr, gis, NG, nullptr, nullptr, 0);
        GP pb = mkGP(layer ? H1hi : H0hi, layer ? H1lo : H0lo, NF,
                     layer ? Whh1h : Whh0h, layer ? Whh1l : Whh0l,
                     nullptr, gh, NG, nullptr, nullptr, 0);
        mma_gemm<64, 0><<<dim3(NG / 64, NB / 128, 2), 128, SMEM64>>>(pa, pb, NF);
        gru_fuse<<<(NB * NF) / 256, 256>>>(gis, gh, layer ? bih1 : bih0, layer ? bhh1 : bhh0,
                                           layer ? H1 : H0, layer ? H1hi : H0hi,
                                           layer ? H1lo : H0lo, nullptr, nullptr);
    };

    // future rollout
    for (int i = 0; i < NTF; i++) {
        cell(fxhi + (size_t)i * NF, fxlo + (size_t)i * NF, (long)NTF * NF, 0);
        cell(H0hi, H0lo, NF, 1);

        rproj_k<<<NB, 256>>>(H1, Wr, br, out_r, i);
        {   GP p = mkGP(H1hi, H1lo, NF, Ws2hi, Ws2lo, bs2,
                        out_s + (size_t)i * NS, (long)NTF * NS, sohi, solo, NS);
            mma_gemm<64, 3><<<dim3(NS / 64, NB / 128, 1), 128, SMEM64>>>(p, p, NF); }
        {   GP p = mkGP(sohi, solo, NS, Wshi, Wslo, bs, nullptr, 0, xhi, xlo, NF);
            mma_gemm<64, 1><<<dim3(NF / 64, NB / 128, 1), 128, SMEM64>>>(p, p, NS); }
        cell(xhi, xlo, NF, 0);
        cell(H0hi, H0lo, NF, 1);
    }
}

// round 6
// speedup vs baseline: 3.2134x; 1.0102x over previous
#include <cuda_runtime.h>
#include <cuda_bf16.h>
#include <cstdint>
#include <math.h>

#define NB 256
#define NTH 32
#define NTF 16
#define NS 512
#define NA 128
#define NF 1024
#define NG 3072
#define NT 65

typedef __nv_bfloat16 bf16;

// ------------------------------ scratch globals -------------------------------
__device__ float g_gi [(size_t)NT * NB * NG];
__device__ float g_fxg[(size_t)NB * NTF * NG];
__device__ float g_H  [4 * NB * NF];                 // [layer][buf][B][F]
__device__ bf16 g_H_hi[4 * NB * NF], g_H_lo[4 * NB * NF];
__device__ bf16 g_xs_hi [(size_t)NT * NB * NF], g_xs_lo [(size_t)NT * NB * NF];
__device__ bf16 g_seq_hi[(size_t)NT * NB * NF], g_seq_lo[(size_t)NT * NB * NF];
__device__ bf16 g_x_hi [NB * NF], g_x_lo [NB * NF];
__device__ bf16 g_fx_hi[NB * NTF * NF], g_fx_lo[NB * NTF * NF];
__device__ bf16 g_so_hi[NB * NS], g_so_lo[NB * NS];
__device__ bf16 g_sb_hi[NB * NTH * NF], g_sb_lo[NB * NTH * NF];
__device__ bf16 g_ab_hi[NB * NTH * NF], g_ab_lo[NB * NTH * NF];
__device__ bf16 g_hs_hi[NB * NTH * NS], g_hs_lo[NB * NTH * NS];
__device__ bf16 g_ha_hi[NB * NTH * NA], g_ha_lo[NB * NTH * NA];
__device__ bf16 g_ps_hi[NB * NS],       g_ps_lo[NB * NS];
__device__ bf16 g_fa_hi[NB * NTF * NA], g_fa_lo[NB * NTF * NA];
__device__ bf16 g_Ws_hi [NF * NS],     g_Ws_lo [NF * NS];
__device__ bf16 g_Wa_hi [NF * NA],     g_Wa_lo [NF * NA];
__device__ bf16 g_Wih_hi[2 * NG * NF], g_Wih_lo[2 * NG * NF];
__device__ bf16 g_Whh_hi[2 * NG * NF], g_Whh_lo[2 * NG * NF];
__device__ bf16 g_Ws2_hi[NS * NF],     g_Ws2_lo[NS * NF];

// ------------------------------- helpers --------------------------------------
__device__ __forceinline__ uint32_t smem_u32(const void* p) {
    uint32_t a;
    asm("{ .reg .u64 t; cvta.to.shared.u64 t, %1; cvt.u32.u64 %0, t; }" : "=r"(a) : "l"(p));
    return a;
}
__device__ __forceinline__ uint32_t lds32(uint32_t a) {
    uint32_t v;
    asm volatile("ld.shared.b32 %0, [%1];" : "=r"(v) : "r"(a));
    return v;
}
#define CPA(d, s) asm volatile("cp.async.cg.shared.global [%0], [%1], 16;" :: "r"(d), "l"(s))
#define CPA_COMMIT() asm volatile("cp.async.commit_group;" ::: "memory")
#define CPA_WAIT1() asm volatile("cp.async.wait_group 1;" ::: "memory")
#define CPA_WAIT0() asm volatile("cp.async.wait_group 0;" ::: "memory")

__device__ __forceinline__ void mma4(float* d, const uint32_t* a, uint32_t b0, uint32_t b1) {
    asm volatile(
        "mma.sync.aligned.m16n8k16.row.col.f32.bf16.bf16.f32 "
        "{%0,%1,%2,%3},{%4,%5,%6,%7},{%8,%9},{%0,%1,%2,%3};"
        : "+f"(d[0]), "+f"(d[1]), "+f"(d[2]), "+f"(d[3])
        : "r"(a[0]), "r"(a[1]), "r"(a[2]), "r"(a[3]), "r"(b0), "r"(b1));
}

// ------------------------- generic GEMM (parallel parts) -----------------------
struct GP {
    const bf16 *Ah, *Al, *Wh, *Wl;
    const float* bias;
    float* C;
    bf16 *Ohi, *Olo;
    long lda, ldc, ldo;
};

template<int BN, int MODE>
__global__ __launch_bounds__(128)
void mma_gemm(GP p, int K)
{
    extern __shared__ __align__(16) char sm[];
    constexpr int APL = 128 * 144;
    constexpr int BPL = BN * 144;
    constexpr int STAGE = 2 * APL + 2 * BPL;
    constexpr int WNT = BN / 16;

    const int tid = threadIdx.x, lane = tid & 31, warp = tid >> 5;
    const int wm = warp & 1, wn = warp >> 1;
    const int m0 = blockIdx.y * 128, n0 = blockIdx.x * BN;
    const uint32_t sb = smem_u32(sm);
    const int lq = lane >> 2, lr = lane & 3;

    float acc[4][WNT][4];
    #pragma unroll
    for (int i = 0; i < 4; i++)
        #pragma unroll
        for (int j = 0; j < WNT; j++)
            #pragma unroll
            for (int q = 0; q < 4; q++) acc[i][j][q] = 0.f;

    auto load_stage = [&](int s, int k0) {
        uint32_t ab = sb + s * STAGE;
        #pragma unroll
        for (int v = tid; v < 1024; v += 128) {
            int row = v >> 3, q = v & 7;
            size_t g = (size_t)(m0 + row) * p.lda + k0 + q * 8;
            uint32_t d = ab + row * 144 + q * 16;
            CPA(d, p.Ah + g);
            CPA(d + APL, p.Al + g);
        }
        #pragma unroll
        for (int v = tid; v < BN * 8; v += 128) {
            int row = v >> 3, q = v & 7;
            size_t g = (size_t)(n0 + row) * K + k0 + q * 8;
            uint32_t d = ab + 2 * APL + row * 144 + q * 16;
            CPA(d, p.Wh + g);
            CPA(d + BPL, p.Wl + g);
        }
    };

    const int NC = K >> 6;
    load_stage(0, 0);
    CPA_COMMIT();

    for (int c = 0; c < NC; c++) {
        if (c + 1 < NC) { load_stage((c + 1) & 1, (c + 1) << 6); CPA_COMMIT(); CPA_WAIT1(); }
        else           { CPA_WAIT0(); }
        __syncthreads();

        const int s = c & 1;
        uint32_t aH = sb + s * STAGE, aL = aH + APL, bH = aL + APL, bL = bH + BPL;
        #pragma unroll
        for (int kk = 0; kk < 4; kk++) {
            const int kb = kk * 32 + lr * 4;
            uint32_t ah[4][4], al[4][4];
            #pragma unroll
            for (int mt = 0; mt < 4; mt++) {
                uint32_t r = (uint32_t)(wm * 64 + mt * 16 + lq) * 144 + kb;
                ah[mt][0] = lds32(aH + r);
                ah[mt][1] = lds32(aH + r + 8 * 144);
                ah[mt][2] = lds32(aH + r + 16);
                ah[mt][3] = lds32(aH + r + 8 * 144 + 16);
                al[mt][0] = lds32(aL + r);
                al[mt][1] = lds32(aL + r + 8 * 144);
                al[mt][2] = lds32(aL + r + 16);
                al[mt][3] = lds32(aL + r + 8 * 144 + 16);
            }
            #pragma unroll
            for (int nt = 0; nt < WNT; nt++) {
                uint32_t r = (uint32_t)(wn * (BN / 2) + nt * 8 + lq) * 144 + kb;
                uint32_t bh0 = lds32(bH + r), bh1 = lds32(bH + r + 16);
                uint32_t bl0 = lds32(bL + r), bl1 = lds32(bL + r + 16);
                #pragma unroll
                for (int mt = 0; mt < 4; mt++) {
                    mma4(acc[mt][nt], ah[mt], bh0, bh1);
                    mma4(acc[mt][nt], ah[mt], bl0, bl1);
                    mma4(acc[mt][nt], al[mt], bh0, bh1);
                }
            }
        }
        __syncthreads();
    }

    #pragma unroll
    for (int mt = 0; mt < 4; mt++) {
        #pragma unroll
        for (int nt = 0; nt < WNT; nt++) {
            int gm = m0 + wm * 64 + mt * 16 + lq;
            int gn = n0 + wn * (BN / 2) + nt * 8 + lr * 2;
            float* a = acc[mt][nt];
            if (MODE == 0) {
                float2 v0; v0.x = a[0]; v0.y = a[1];
                float2 v1; v1.x = a[2]; v1.y = a[3];
                *reinterpret_cast<float2*>(p.C + (size_t)gm * p.ldc + gn) = v0;
                *reinterpret_cast<float2*>(p.C + (size_t)(gm + 8) * p.ldc + gn) = v1;
            } else {
                float b0 = p.bias[gn], b1 = p.bias[gn + 1];
                float v00 = tanhf(a[0] + b0), v01 = tanhf(a[1] + b1);
                float v10 = tanhf(a[2] + b0), v11 = tanhf(a[3] + b1);
                __nv_bfloat162 h0, l0, h1, l1;
                h0.x = __float2bfloat16(v00); h0.y = __float2bfloat16(v01);
                l0.x = __float2bfloat16(v00 - __bfloat162float(h0.x));
                l0.y = __float2bfloat16(v01 - __bfloat162float(h0.y));
                h1.x = __float2bfloat16(v10); h1.y = __float2bfloat16(v11);
                l1.x = __float2bfloat16(v10 - __bfloat162float(h1.x));
                l1.y = __float2bfloat16(v11 - __bfloat162float(h1.y));
                *reinterpret_cast<__nv_bfloat162*>(p.Ohi + (size_t)gm * p.ldo + gn) = h0;
                *reinterpret_cast<__nv_bfloat162*>(p.Olo + (size_t)gm * p.ldo + gn) = l0;
                *reinterpret_cast<__nv_bfloat162*>(p.Ohi + (size_t)(gm + 8) * p.ldo + gn) = h1;
                *reinterpret_cast<__nv_bfloat162*>(p.Olo + (size_t)(gm + 8) * p.ldo + gn) = l1;
                if (MODE == 3) {
                    float2 v0; v0.x = v00; v0.y = v01;
                    float2 v1; v1.x = v10; v1.y = v11;
                    *reinterpret_cast<float2*>(p.C + (size_t)gm * p.ldc + gn) = v0;
                    *reinterpret_cast<float2*>(p.C + (size_t)(gm + 8) * p.ldc + gn) = v1;
                }
            }
        }
    }
}

// ------------------- fused GRU step: gh GEMM (+gi GEMM) + gates ----------------
// Block tile: 64 batch rows x (32 f-cols x 3 gates = 96 B-rows).  4 warps, each
// warp owns one 8-wide f-group x 3 gates.  B smem row rr = q*24 + g*8 + u maps
// to global W row g*1024 + f0 + q*8 + u.  Grid (NF/32, NB/64) = (32, 4).
// DUAL=1: also computes gi = X @ Wih^T in-kernel (second acc set).
// !DUAL: reads precomputed gi at giB[b*giS + g*1024 + f].
__device__ __forceinline__ void gs_compute(uint32_t aH, uint32_t aL, uint32_t bH, uint32_t bL,
                                           int wn, int lq, int kb, float (*acc)[3][4])
{
    uint32_t ah[4][4], al[4][4];
    #pragma unroll
    for (int mt = 0; mt < 4; mt++) {
        uint32_t r = (uint32_t)(mt * 16 + lq) * 144 + kb;
        ah[mt][0] = lds32(aH + r);
        ah[mt][1] = lds32(aH + r + 8 * 144);
        ah[mt][2] = lds32(aH + r + 16);
        ah[mt][3] = lds32(aH + r + 8 * 144 + 16);
        al[mt][0] = lds32(aL + r);
        al[mt][1] = lds32(aL + r + 8 * 144);
        al[mt][2] = lds32(aL + r + 16);
        al[mt][3] = lds32(aL + r + 8 * 144 + 16);
    }
    #pragma unroll
    for (int nt = 0; nt < 3; nt++) {
        uint32_t r = (uint32_t)(wn * 24 + nt * 8 + lq) * 144 + kb;
        uint32_t bh0 = lds32(bH + r), bh1 = lds32(bH + r + 16);
        uint32_t bl0 = lds32(bL + r), bl1 = lds32(bL + r + 16);
        #pragma unroll
        for (int mt = 0; mt < 4; mt++) {
            mma4(acc[mt][nt], ah[mt], bh0, bh1);
            mma4(acc[mt][nt], ah[mt], bl0, bl1);
            mma4(acc[mt][nt], al[mt], bh0, bh1);
        }
    }
}

template<int DUAL, int WSEQ>
__global__ __launch_bounds__(128)
void gru_step(const bf16* __restrict__ Hh, const bf16* __restrict__ Hl,
              const bf16* __restrict__ Wh_h, const bf16* __restrict__ Wh_l,
              const bf16* __restrict__ Xh, const bf16* __restrict__ Xl,
              const bf16* __restrict__ Wi_h, const bf16* __restrict__ Wi_l,
              const float* __restrict__ giB, long giS,
              const float* __restrict__ bih, const float* __restrict__ bhh,
              const float* __restrict__ hOld,
              float* __restrict__ hNew, bf16* __restrict__ nhi, bf16* __restrict__ nlo,
              bf16* __restrict__ shi, bf16* __restrict__ slo)
{
    extern __shared__ __align__(16) char sm[];
    constexpr int APL = 64 * 144, BPL = 96 * 144;
    constexpr int NP = DUAL ? 4 : 2;
    constexpr int STAGE = NP * (APL + BPL);

    const int tid = threadIdx.x, lane = tid & 31, wn = tid >> 5;
    const int lq = lane >> 2, lr = lane & 3;
    const int f0 = blockIdx.x * 32, m0 = blockIdx.y * 64;
    const uint32_t sb = smem_u32(sm);

    float acch[4][3][4];
    float acci[4][3][4];
    #pragma unroll
    for (int i = 0; i < 4; i++)
        #pragma unroll
        for (int j = 0; j < 3; j++)
            #pragma unroll
            for (int q = 0; q < 4; q++) { acch[i][j][q] = 0.f; acci[i][j][q] = 0.f; }

    auto load_stage = [&](int s, int k0) {
        uint32_t base = sb + s * STAGE;
        #pragma unroll
        for (int v = tid; v < 512; v += 128) {
            int row = v >> 3, q = v & 7;
            size_t g = (size_t)(m0 + row) * NF + k0 + q * 8;
            uint32_t d = base + row * 144 + q * 16;
            CPA(d, Hh + g);
            CPA(d + APL, Hl + g);
            if (DUAL) { CPA(d + 2 * APL, Xh + g); CPA(d + 3 * APL, Xl + g); }
        }
        uint32_t bb = base + NP * APL;
        #pragma unroll
        for (int v = tid; v < 768; v += 128) {
            int rr = v >> 3, q8 = v & 7;
            int qq = rr / 24, rem = rr - qq * 24;
            int g = rem >> 3, u = rem & 7;
            size_t R = (size_t)(g * 1024 + f0 + qq * 8 + u) * NF + k0 + q8 * 8;
            uint32_t d = bb + rr * 144 + q8 * 16;
            CPA(d, Wh_h + R);
            CPA(d + BPL, Wh_l + R);
            if (DUAL) { CPA(d + 2 * BPL, Wi_h + R); CPA(d + 3 * BPL, Wi_l + R); }
        }
    };

    const int NC = NF >> 6;          // 16
    load_stage(0, 0);
    CPA_COMMIT();

    for (int c = 0; c < NC; c++) {
        if (c + 1 < NC) { load_stage((c + 1) & 1, (c + 1) << 6); CPA_COMMIT(); CPA_WAIT1(); }
        else           { CPA_WAIT0(); }
        __syncthreads();

        uint32_t base = sb + (c & 1) * STAGE;
        uint32_t aH = base, aL = base + APL;
        uint32_t bb = base + NP * APL;
        uint32_t bH = bb, bL = bb + BPL;
        #pragma unroll
        for (int kk = 0; kk < 4; kk++) {
            const int kb = kk * 32 + lr * 4;
            gs_compute(aH, aL, bH, bL, wn, lq, kb, acch);
            if (DUAL)
                gs_compute(base + 2 * APL, base + 3 * APL,
                           bb + 2 * BPL, bb + 3 * BPL, wn, lq, kb, acci);
        }
        __syncthreads();
    }

    // ---- fused GRU gate epilogue ----
    const int fc = f0 + wn * 8 + lr * 2;     // this thread's f (col pair fc, fc+1)
    float bi[3][2], bh_[3][2];
    #pragma unroll
    for (int g = 0; g < 3; g++) {
        bi[g][0]  = bih[g * 1024 + fc];  bi[g][1]  = bih[g * 1024 + fc + 1];
        bh_[g][0] = bhh[g * 1024 + fc];  bh_[g][1] = bhh[g * 1024 + fc + 1];
    }
    #pragma unroll
    for (int mt = 0; mt < 4; mt++) {
        #pragma unroll
        for (int half = 0; half < 2; half++) {
            int b = m0 + mt * 16 + lq + half * 8;
            float o[2];
            #pragma unroll
            for (int cidx = 0; cidx < 2; cidx++) {
                int k = half * 2 + cidx;
                int f = fc + cidx;
                float hr = acch[mt][0][k], hz = acch[mt][1][k], hn = acch[mt][2][k];
                float ir, iz, in_;
                if (DUAL) {
                    ir = acci[mt][0][k]; iz = acci[mt][1][k]; in_ = acci[mt][2][k];
                } else {
                    const float* gp = giB + (size_t)b * giS;
                    ir = gp[f]; iz = gp[1024 + f]; in_ = gp[2048 + f];
                }
                float r = 1.f / (1.f + expf(-(ir + bi[0][cidx] + hr + bh_[0][cidx])));
                float z = 1.f / (1.f + expf(-(iz + bi[1][cidx] + hz + bh_[1][cidx])));
                float n = tanhf(in_ + bi[2][cidx] + r * (hn + bh_[2][cidx]));
                float ho = hOld[(size_t)b * NF + f];
                o[cidx] = (1.f - z) * n + z * ho;
            }
            float2 o2; o2.x = o[0]; o2.y = o[1];
            *reinterpret_cast<float2*>(hNew + (size_t)b * NF + fc) = o2;
            __nv_bfloat162 hh, ll;
            hh.x = __float2bfloat16(o[0]); hh.y = __float2bfloat16(o[1]);
            ll.x = __float2bfloat16(o[0] - __bfloat162float(hh.x));
            ll.y = __float2bfloat16(o[1] - __bfloat162float(hh.y));
            *reinterpret_cast<__nv_bfloat162*>(nhi + (size_t)b * NF + fc) = hh;
            *reinterpret_cast<__nv_bfloat162*>(nlo + (size_t)b * NF + fc) = ll;
            if (WSEQ) {
                *reinterpret_cast<__nv_bfloat162*>(shi + (size_t)b * NF + fc) = hh;
                *reinterpret_cast<__nv_bfloat162*>(slo + (size_t)b * NF + fc) = ll;
            }
        }
    }
}

// ------------------------------ small kernels ----------------------------------
__global__ void interleave_k(const bf16* __restrict__ sh, const bf16* __restrict__ sl,
                             const bf16* __restrict__ ah, const bf16* __restrict__ al,
                             bf16* __restrict__ xh, bf16* __restrict__ xl)
{
    int i = blockIdx.x * blockDim.x + threadIdx.x;
    int t = i / (NB * NF / 2);
    int rem = i % (NB * NF / 2);
    int b = rem / (NF / 2), f2 = rem % (NF / 2);
    int u = t >> 1;
    size_t src = (size_t)(b * NTH + u) * (NF / 2) + f2;
    const uint32_t* ph = reinterpret_cast<const uint32_t*>((t & 1) ? ah : sh);
    const uint32_t* pl = reinterpret_cast<const uint32_t*>((t & 1) ? al : sl);
    reinterpret_cast<uint32_t*>(xh)[i] = ph[src];
    reinterpret_cast<uint32_t*>(xl)[i] = pl[src];
}

__global__ void rproj_k(const float* __restrict__ H1, const float* __restrict__ Wr,
                        const float* __restrict__ br, float* __restrict__ out_r, int step)
{
    __shared__ float red[256];
    int b = blockIdx.x;
    float p = 0.f;
    for (int k = threadIdx.x; k < NF; k += 256) p += H1[(size_t)b * NF + k] * Wr[k];
    red[threadIdx.x] = p;
    __syncthreads();
    for (int s = 128; s > 0; s >>= 1) {
        if (threadIdx.x < s) red[threadIdx.x] += red[threadIdx.x + s];
        __syncthreads();
    }
    if (threadIdx.x == 0)
        out_r[b * NTF + step] = 1.f / (1.f + expf(-(red[0] + br[0])));
}

__global__ void split_k(const float* __restrict__ x, bf16* __restrict__ hi,
                        bf16* __restrict__ lo, int n)
{
    int i = blockIdx.x * blockDim.x + threadIdx.x;
    if (i < n) {
        float v = x[i];
        bf16 h = __float2bfloat16(v);
        hi[i] = h;
        lo[i] = __float2bfloat16(v - __bfloat162float(h));
    }
}

__global__ void zeroH_k(float* h, bf16* hi, bf16* lo, int n)
{
    int i = blockIdx.x * blockDim.x + threadIdx.x;
    if (i < n) { h[i] = 0.f; hi[i] = __float2bfloat16(0.f); lo[i] = __float2bfloat16(0.f); }
}

// ----------------------------------- host --------------------------------------
static const int SMEM128 = 2 * (2 * 128 * 144 + 2 * 128 * 144);   // 147456
static const int SMEM64  = 2 * (2 * 128 * 144 + 2 *  64 * 144);   // 110592
static const int SMS     = 2 * 2 * (64 * 144 + 96 * 144);         // 92160
static const int SMD     = 2 * 4 * (64 * 144 + 96 * 144);         // 184320

static inline GP mkGP(const bf16* Ah, const bf16* Al, long lda,
                      const bf16* Wh, const bf16* Wl,
                      const float* bias, float* C, long ldc,
                      bf16* Ohi, bf16* Olo, long ldo)
{
    GP p; p.Ah = Ah; p.Al = Al; p.Wh = Wh; p.Wl = Wl; p.bias = bias;
    p.C = C; p.Ohi = Ohi; p.Olo = Olo; p.lda = lda; p.ldc = ldc; p.ldo = ldo;
    return p;
}

extern "C" void kernel_launch(void* const* d_in, const int* in_sizes, int n_in,
                              void* d_out, int out_size)
{
    (void)in_sizes; (void)n_in; (void)out_size;
    const float* history_s = (const float*)d_in[0];
    const float* history_a = (const float*)d_in[1];
    const float* present_s = (const float*)d_in[2];
    const float* future_a  = (const float*)d_in[3];
    const float* Ws  = (const float*)d_in[4];
    const float* bs  = (const float*)d_in[5];
    const float* Wa  = (const float*)d_in[6];
    const float* ba  = (const float*)d_in[7];
    const float* Wih = (const float*)d_in[8];
    const float* Whh = (const float*)d_in[9];
    const float* bih = (const float*)d_in[10];
    const float* bhh = (const float*)d_in[11];
    const float* Wr  = (const float*)d_in[12];
    const float* br  = (const float*)d_in[13];
    const float* Ws2 = (const float*)d_in[14];
    const float* bs2 = (const float*)d_in[15];

    float* out_r = (float*)d_out;
    float* out_s = (float*)d_out + NB * NTF;

    float *gi, *fxg, *H;
    bf16 *Hhi, *Hlo, *xshi, *xslo, *seqhi, *seqlo, *xhi, *xlo, *fxhi, *fxlo, *sohi, *solo;
    bf16 *sbhi, *sblo, *abhi, *ablo;
    bf16 *hshi, *hslo, *hahi, *halo, *pshi, *pslo, *fahi, *falo;
    bf16 *Wshi, *Wslo, *Wahi, *Walo, *Wihhi, *Wihlo, *Whhhi, *Whhlo, *Ws2hi, *Ws2lo;
    cudaGetSymbolAddress((void**)&gi, g_gi);     cudaGetSymbolAddress((void**)&fxg, g_fxg);
    cudaGetSymbolAddress((void**)&H, g_H);
    cudaGetSymbolAddress((void**)&Hhi, g_H_hi);  cudaGetSymbolAddress((void**)&Hlo, g_H_lo);
    cudaGetSymbolAddress((void**)&xshi, g_xs_hi); cudaGetSymbolAddress((void**)&xslo, g_xs_lo);
    cudaGetSymbolAddress((void**)&seqhi, g_seq_hi); cudaGetSymbolAddress((void**)&seqlo, g_seq_lo);
    cudaGetSymbolAddress((void**)&xhi, g_x_hi);  cudaGetSymbolAddress((void**)&xlo, g_x_lo);
    cudaGetSymbolAddress((void**)&fxhi, g_fx_hi); cudaGetSymbolAddress((void**)&fxlo, g_fx_lo);
    cudaGetSymbolAddress((void**)&sohi, g_so_hi); cudaGetSymbolAddress((void**)&solo, g_so_lo);
    cudaGetSymbolAddress((void**)&sbhi, g_sb_hi); cudaGetSymbolAddress((void**)&sblo, g_sb_lo);
    cudaGetSymbolAddress((void**)&abhi, g_ab_hi); cudaGetSymbolAddress((void**)&ablo, g_ab_lo);
    cudaGetSymbolAddress((void**)&hshi, g_hs_hi); cudaGetSymbolAddress((void**)&hslo, g_hs_lo);
    cudaGetSymbolAddress((void**)&hahi, g_ha_hi); cudaGetSymbolAddress((void**)&halo, g_ha_lo);
    cudaGetSymbolAddress((void**)&pshi, g_ps_hi); cudaGetSymbolAddress((void**)&pslo, g_ps_lo);
    cudaGetSymbolAddress((void**)&fahi, g_fa_hi); cudaGetSymbolAddress((void**)&falo, g_fa_lo);
    cudaGetSymbolAddress((void**)&Wshi, g_Ws_hi); cudaGetSymbolAddress((void**)&Wslo, g_Ws_lo);
    cudaGetSymbolAddress((void**)&Wahi, g_Wa_hi); cudaGetSymbolAddress((void**)&Walo, g_Wa_lo);
    cudaGetSymbolAddress((void**)&Wihhi, g_Wih_hi); cudaGetSymbolAddress((void**)&Wihlo, g_Wih_lo);
    cudaGetSymbolAddress((void**)&Whhhi, g_Whh_hi); cudaGetSymbolAddress((void**)&Whhlo, g_Whh_lo);
    cudaGetSymbolAddress((void**)&Ws2hi, g_Ws2_hi); cudaGetSymbolAddress((void**)&Ws2lo, g_Ws2_lo);

    cudaFuncSetAttribute(mma_gemm<128, 0>, cudaFuncAttributeMaxDynamicSharedMemorySize, SMEM128);
    cudaFuncSetAttribute(mma_gemm<128, 1>, cudaFuncAttributeMaxDynamicSharedMemorySize, SMEM128);
    cudaFuncSetAttribute(mma_gemm<64, 1>,  cudaFuncAttributeMaxDynamicSharedMemorySize, SMEM64);
    cudaFuncSetAttribute(mma_gemm<64, 3>,  cudaFuncAttributeMaxDynamicSharedMemorySize, SMEM64);
    cudaFuncSetAttribute(gru_step<0, 0>, cudaFuncAttributeMaxDynamicSharedMemorySize, SMS);
    cudaFuncSetAttribute(gru_step<0, 1>, cudaFuncAttributeMaxDynamicSharedMemorySize, SMS);
    cudaFuncSetAttribute(gru_step<1, 0>, cudaFuncAttributeMaxDynamicSharedMemorySize, SMD);

    auto split = [&](const float* x, bf16* hi, bf16* lo, long n) {
        split_k<<<(int)((n + 255) / 256), 256>>>(x, hi, lo, (int)n);
    };
    split(history_s, hshi, hslo, (long)NB * NTH * NS);
    split(history_a, hahi, halo, (long)NB * NTH * NA);
    split(present_s, pshi, pslo, (long)NB * NS);
    split(future_a,  fahi, falo, (long)NB * NTF * NA);
    split(Ws,  Wshi,  Wslo,  (long)NF * NS);
    split(Wa,  Wahi,  Walo,  (long)NF * NA);
    split(Wih, Wihhi, Wihlo, (long)2 * NG * NF);
    split(Whh, Whhhi, Whhlo, (long)2 * NG * NF);
    split(Ws2, Ws2hi, Ws2lo, (long)NS * NF);
    zeroH_k<<<(4 * NB * NF + 255) / 256, 256>>>(H, Hhi, Hlo, 4 * NB * NF);

    const bf16 *Wih0h = Wihhi, *Wih0l = Wihlo;
    const bf16 *Wih1h = Wihhi + (size_t)NG * NF, *Wih1l = Wihlo + (size_t)NG * NF;
    const bf16 *Whh0h = Whhhi, *Whh0l = Whhlo;
    const bf16 *Whh1h = Whhhi + (size_t)NG * NF, *Whh1l = Whhlo + (size_t)NG * NF;
    const float *bih0 = bih, *bih1 = bih + NG, *bhh0 = bhh, *bhh1 = bhh + NG;

    // ping-pong hidden-state buffers: index (layer*2 + buf)
    auto Hf  = [&](int l, int p) { return H   + (size_t)(l * 2 + p) * NB * NF; };
    auto Hfh = [&](int l, int p) { return Hhi + (size_t)(l * 2 + p) * NB * NF; };
    auto Hfl = [&](int l, int p) { return Hlo + (size_t)(l * 2 + p) * NB * NF; };
    int p0 = 0, p1 = 0;

    const dim3 GS(NF / 32, NB / 64);       // (32, 4) = 128 CTAs

    // embeddings (parallel)
    {   GP p = mkGP(hshi, hslo, NS, Wshi, Wslo, bs, nullptr, 0, sbhi, sblo, NF);
        mma_gemm<128, 1><<<dim3(NF / 128, (NB * NTH) / 128), 128, SMEM128>>>(p, NS); }
    {   GP p = mkGP(hahi, halo, NA, Wahi, Walo, ba, nullptr, 0, abhi, ablo, NF);
        mma_gemm<128, 1><<<dim3(NF / 128, (NB * NTH) / 128), 128, SMEM128>>>(p, NA); }
    {   GP p = mkGP(pshi, pslo, NS, Wshi, Wslo, bs, nullptr, 0,
                    xshi + (size_t)64 * NB * NF, xslo + (size_t)64 * NB * NF, NF);
        mma_gemm<64, 1><<<dim3(NF / 64, NB / 128), 128, SMEM64>>>(p, NS); }
    {   // all 16 future action embeddings at once: [B*TF, A] -> [B*TF, F]
        GP p = mkGP(fahi, falo, NA, Wahi, Walo, ba, nullptr, 0, fxhi, fxlo, NF);
        mma_gemm<128, 1><<<dim3(NF / 128, (NB * NTF) / 128), 128, SMEM128>>>(p, NA); }
    interleave_k<<<(64 * NB * NF / 2) / 256, 256>>>(sbhi, sblo, abhi, ablo, xshi, xslo);
    {   // hoisted: gi for ALL future first-cells: fx @ Wih0^T
        GP p = mkGP(fxhi, fxlo, NF, Wih0h, Wih0l, nullptr, fxg, NG, nullptr, nullptr, 0);
        mma_gemm<128, 0><<<dim3(NG / 128, (NB * NTF) / 128), 128, SMEM128>>>(p, NF); }

    // layer 0 over prefix
    {   GP p = mkGP(xshi, xslo, NF, Wih0h, Wih0l, nullptr, gi, NG, nullptr, nullptr, 0);
        mma_gemm<128, 0><<<dim3(NG / 128, (NT * NB) / 128), 128, SMEM128>>>(p, NF); }
    for (int t = 0; t < NT; t++) {
        gru_step<0, 1><<<GS, 128, SMS>>>(Hfh(0, p0), Hfl(0, p0), Whh0h, Whh0l,
            nullptr, nullptr, nullptr, nullptr,
            gi + (size_t)t * NB * NG, (long)NG, bih0, bhh0,
            Hf(0, p0), Hf(0, p0 ^ 1), Hfh(0, p0 ^ 1), Hfl(0, p0 ^ 1),
            seqhi + (size_t)t * NB * NF, seqlo + (size_t)t * NB * NF);
        p0 ^= 1;
    }
    // layer 1 over prefix
    {   GP p = mkGP(seqhi, seqlo, NF, Wih1h, Wih1l, nullptr, gi, NG, nullptr, nullptr, 0);
        mma_gemm<128, 0><<<dim3(NG / 128, (NT * NB) / 128), 128, SMEM128>>>(p, NF); }
    for (int t = 0; t < NT; t++) {
        gru_step<0, 0><<<GS, 128, SMS>>>(Hfh(1, p1), Hfl(1, p1), Whh1h, Whh1l,
            nullptr, nullptr, nullptr, nullptr,
            gi + (size_t)t * NB * NG, (long)NG, bih1, bhh1,
            Hf(1, p1), Hf(1, p1 ^ 1), Hfh(1, p1 ^ 1), Hfl(1, p1 ^ 1),
            nullptr, nullptr);
        p1 ^= 1;
    }

    // dual-GEMM fused cell: gi = X@Wih^T computed in-kernel
    auto dcell = [&](const bf16* Xh, const bf16* Xl, int layer) {
        int& pp = layer ? p1 : p0;
        gru_step<1, 0><<<GS, 128, SMD>>>(
            Hfh(layer, pp), Hfl(layer, pp),
            layer ? Whh1h : Whh0h, layer ? Whh1l : Whh0l,
            Xh, Xl, layer ? Wih1h : Wih0h, layer ? Wih1l : Wih0l,
            nullptr, 0, layer ? bih1 : bih0, layer ? bhh1 : bhh0,
            Hf(layer, pp), Hf(layer, pp ^ 1), Hfh(layer, pp ^ 1), Hfl(layer, pp ^ 1),
            nullptr, nullptr);
        pp ^= 1;
    };

    // future rollout
    for (int i = 0; i < NTF; i++) {
        // layer0 first cell: gi precomputed in fxg (row b*NTF+i)
        gru_step<0, 0><<<GS, 128, SMS>>>(Hfh(0, p0), Hfl(0, p0), Whh0h, Whh0l,
            nullptr, nullptr, nullptr, nullptr,
            fxg + (size_t)i * NG, (long)NTF * NG, bih0, bhh0,
            Hf(0, p0), Hf(0, p0 ^ 1), Hfh(0, p0 ^ 1), Hfl(0, p0 ^ 1),
            nullptr, nullptr);
        p0 ^= 1;
        dcell(Hfh(0, p0), Hfl(0, p0), 1);

        rproj_k<<<NB, 256>>>(Hf(1, p1), Wr, br, out_r, i);
        {   GP p = mkGP(Hfh(1, p1), Hfl(1, p1), NF, Ws2hi, Ws2lo, bs2,
                        out_s + (size_t)i * NS, (long)NTF * NS, sohi, solo, NS);
            mma_gemm<64, 3><<<dim3(NS / 64, NB / 128), 128, SMEM64>>>(p, NF); }
        {   GP p = mkGP(sohi, solo, NS, Wshi, Wslo, bs, nullptr, 0, xhi, xlo, NF);
            mma_gemm<64, 1><<<dim3(NF / 64, NB / 128), 128, SMEM64>>>(p, NS); }
        dcell(xhi, xlo, 0);
        dcell(Hfh(0, p0), Hfl(0, p0), 1);
    }
}